// round 5
// baseline (speedup 1.0000x reference)
#include <cuda_runtime.h>
#include <cstdint>

// ---------------- problem constants ----------------
#define BATCH   16
#define N1      4096
#define N2      1024
#define C2      256
#define OUTCH   256
#define KTOT    4096
#define SPLITK  4
#define KPER    (KTOT/SPLITK)   // 1024
#define KT      32              // K tile
#define NT      (KPER/KT)       // 32 tiles
#define BN_EPS  1e-5f

// smem layout (floats): Ws[2][128*36], Bs[2][32*136]
// WS_STRIDE 36  -> A-frag LDS banks (4g+kq) mod 32 : conflict-free
// BS_STRIDE 136 -> B-frag LDS banks (8kq+g) mod 32 : conflict-free (fix vs 132)
#define WS_STRIDE 36
#define BS_STRIDE 136
#define WS_BUF    (128*WS_STRIDE)        // 4608 floats
#define BS_BUF    (32*BS_STRIDE)         // 4352 floats
#define SMEM_FLOATS (2*WS_BUF + 2*BS_BUF)  // 17920 floats = 71680 B

// ---------------- device scratch ----------------
__device__ int    g_idx[BATCH * N1 * 3];
__device__ float  g_w  [BATCH * N1 * 3];
__device__ float  g_Wtf[(size_t)OUTCH * KTOT];                 // 4 MB  tf32-rounded W
__device__ float  g_interp[(size_t)BATCH * N1 * C2];           // 67 MB tf32-rounded A[b][n][c]
__device__ float  g_yp[SPLITK][(size_t)BATCH * OUTCH * C2];    // 16 MB partials
__device__ float  g_y [(size_t)BATCH * OUTCH * C2];
__device__ float  g_sum[C2];
__device__ float  g_sumsq[C2];

// ---------------- helpers ----------------
__device__ __forceinline__ uint32_t smem_u32(const void* p) {
    uint32_t a;
    asm("{ .reg .u64 t; cvta.to.shared.u64 t, %1; cvt.u32.u64 %0, t; }" : "=r"(a) : "l"(p));
    return a;
}
__device__ __forceinline__ float tf32r(float x) {
    uint32_t u;
    asm("cvt.rna.tf32.f32 %0, %1;" : "=r"(u) : "f"(x));
    return __uint_as_float(u);
}
__device__ __forceinline__ void cp16(uint32_t dst, const void* src) {
    asm volatile("cp.async.cg.shared.global [%0], [%1], 16;" :: "r"(dst), "l"(src) : "memory");
}
#define CP_COMMIT()  asm volatile("cp.async.commit_group;" ::: "memory")
#define CP_WAIT(n)   asm volatile("cp.async.wait_group %0;" :: "n"(n) : "memory")

__device__ __forceinline__ void mma_tf32(float* d, const uint32_t* a, const uint32_t* b) {
    asm volatile(
        "mma.sync.aligned.m16n8k8.row.col.f32.tf32.tf32.f32 "
        "{%0,%1,%2,%3}, {%4,%5,%6,%7}, {%8,%9}, {%0,%1,%2,%3};"
        : "+f"(d[0]), "+f"(d[1]), "+f"(d[2]), "+f"(d[3])
        : "r"(a[0]), "r"(a[1]), "r"(a[2]), "r"(a[3]), "r"(b[0]), "r"(b[1]));
}

// ---------------- kernel 0: zero BN accumulators ----------------
__global__ void zero_stats_kernel() {
    int c = threadIdx.x;
    g_sum[c] = 0.f;
    g_sumsq[c] = 0.f;
}

// ---------------- kernel 0b: W -> tf32-rounded copy ----------------
__global__ void convW_kernel(const float* __restrict__ W1) {
    int i = blockIdx.x * 256 + threadIdx.x;   // float4 index
    float4 v = ((const float4*)W1)[i];
    ((float4*)g_Wtf)[i] = make_float4(tf32r(v.x), tf32r(v.y), tf32r(v.z), tf32r(v.w));
}

// ---------------- kernel 1: 3-NN + weights (2 points / thread) ----------------
__global__ __launch_bounds__(256)
void topk_kernel(const float* __restrict__ xyz1,
                 const float* __restrict__ xyz2) {
    __shared__ float sx[N2], sy[N2], sz[N2];
    int b = blockIdx.x >> 3;
    int chunk = blockIdx.x & 7;

    const float* p2 = xyz2 + (size_t)b * N2 * 3;
    for (int j = threadIdx.x; j < N2; j += 256) {
        sx[j] = p2[j * 3 + 0]; sy[j] = p2[j * 3 + 1]; sz[j] = p2[j * 3 + 2];
    }
    __syncthreads();

    int nA = chunk * 512 + threadIdx.x;
    int nB = nA + 256;
    const float* pA = xyz1 + ((size_t)b * N1 + nA) * 3;
    const float* pB = xyz1 + ((size_t)b * N1 + nB) * 3;
    float ax = pA[0], ay = pA[1], az = pA[2];
    float bx = pB[0], by = pB[1], bz = pB[2];

    float a0 = 3.4e38f, a1 = 3.4e38f, a2 = 3.4e38f;
    int   ai0 = 0, ai1 = 0, ai2 = 0;
    float b0 = 3.4e38f, b1 = 3.4e38f, b2 = 3.4e38f;
    int   bi0 = 0, bi1 = 0, bi2 = 0;

#pragma unroll 4
    for (int j = 0; j < N2; ++j) {
        float qx = sx[j], qy = sy[j], qz = sz[j];
        float dx = ax - qx, dy = ay - qy, dz = az - qz;
        float dA = fmaf(dx, dx, fmaf(dy, dy, dz * dz));
        float ex = bx - qx, ey = by - qy, ez = bz - qz;
        float dB = fmaf(ex, ex, fmaf(ey, ey, ez * ez));
        if (dA < a2) {
            if (dA < a1) {
                a2 = a1; ai2 = ai1;
                if (dA < a0) { a1 = a0; ai1 = ai0; a0 = dA; ai0 = j; }
                else         { a1 = dA; ai1 = j; }
            } else { a2 = dA; ai2 = j; }
        }
        if (dB < b2) {
            if (dB < b1) {
                b2 = b1; bi2 = bi1;
                if (dB < b0) { b1 = b0; bi1 = bi0; b0 = dB; bi0 = j; }
                else         { b1 = dB; bi1 = j; }
            } else { b2 = dB; bi2 = j; }
        }
    }
    {
        float r0 = 1.f / (a0 + 1e-8f), r1 = 1.f / (a1 + 1e-8f), r2 = 1.f / (a2 + 1e-8f);
        float inv = 1.f / (r0 + r1 + r2);
        size_t base = ((size_t)b * N1 + nA) * 3;
        g_idx[base + 0] = ai0; g_idx[base + 1] = ai1; g_idx[base + 2] = ai2;
        g_w  [base + 0] = r0 * inv; g_w[base + 1] = r1 * inv; g_w[base + 2] = r2 * inv;
    }
    {
        float r0 = 1.f / (b0 + 1e-8f), r1 = 1.f / (b1 + 1e-8f), r2 = 1.f / (b2 + 1e-8f);
        float inv = 1.f / (r0 + r1 + r2);
        size_t base = ((size_t)b * N1 + nB) * 3;
        g_idx[base + 0] = bi0; g_idx[base + 1] = bi1; g_idx[base + 2] = bi2;
        g_w  [base + 0] = r0 * inv; g_w[base + 1] = r1 * inv; g_w[base + 2] = r2 * inv;
    }
}

// ---------------- kernel 2: interpolation (tf32-rounded) -> A[b][n][c] ----------------
__global__ void interp_kernel(const float* __restrict__ x2) {
    int pt   = blockIdx.x * 4 + (threadIdx.x >> 6);
    int lane = threadIdx.x & 63;
    int b = pt >> 12;

    size_t base = (size_t)pt * 3;
    int i0 = g_idx[base + 0], i1 = g_idx[base + 1], i2 = g_idx[base + 2];
    float w0 = g_w[base + 0], w1 = g_w[base + 1], w2 = g_w[base + 2];

    const float* xb = x2 + (size_t)b * N2 * C2;
    int c = lane * 4;
    float4 v0 = *(const float4*)(xb + (size_t)i0 * C2 + c);
    float4 v1 = *(const float4*)(xb + (size_t)i1 * C2 + c);
    float4 v2 = *(const float4*)(xb + (size_t)i2 * C2 + c);

    float4 r;
    r.x = tf32r(fmaf(w0, v0.x, fmaf(w1, v1.x, w2 * v2.x)));
    r.y = tf32r(fmaf(w0, v0.y, fmaf(w1, v1.y, w2 * v2.y)));
    r.z = tf32r(fmaf(w0, v0.z, fmaf(w1, v1.z, w2 * v2.z)));
    r.w = tf32r(fmaf(w0, v0.w, fmaf(w1, v1.w, w2 * v2.w)));
    *(float4*)(g_interp + (size_t)pt * C2 + c) = r;
}

// ---------------- kernel 3: tf32 mma.sync GEMM ----------------
// grid = b(16) x Mtile(2) x Ntile(2) x splitK(4) = 256 CTAs, 256 threads
__global__ __launch_bounds__(256, 2)
void gemm_mma_kernel() {
    extern __shared__ float sm[];
    const uint32_t smb = smem_u32(sm);

    int bid = blockIdx.x;
    int s   = bid & 3;
    int mtb = (bid >> 2) & 1;
    int ntb = (bid >> 3) & 1;
    int b   = bid >> 4;
    int o0 = mtb * 128, c0 = ntb * 128, k0 = s * KPER;

    int t = threadIdx.x;
    int w = t >> 5, lane = t & 31;
    int g = lane >> 2, kq = lane & 3;
    int warp_m = (w & 3) * 32;
    int warp_n = (w >> 2) * 64;

    const float* Wg = g_Wtf + (size_t)o0 * KTOT + k0;
    const float* Bg = g_interp + ((size_t)b * N1 + k0) * C2 + c0;

    // per-thread load slots (4 x float4 each for W and B)
    int wm[4], wq4[4], bk[4], bq4[4];
    uint32_t wdst[4], bdst[4];
#pragma unroll
    for (int i = 0; i < 4; ++i) {
        int li = i * 256 + t;
        wm[i]  = li >> 3;        wq4[i] = (li & 7) * 4;
        bk[i]  = li >> 5;        bq4[i] = (li & 31) * 4;
        wdst[i] = (uint32_t)((wm[i] * WS_STRIDE + wq4[i]) * 4);
        bdst[i] = (uint32_t)((2 * WS_BUF + bk[i] * BS_STRIDE + bq4[i]) * 4);
    }

    float acc[2][8][4];
#pragma unroll
    for (int mt = 0; mt < 2; ++mt)
#pragma unroll
        for (int nt = 0; nt < 8; ++nt)
#pragma unroll
            for (int r = 0; r < 4; ++r) acc[mt][nt][r] = 0.f;

    // issue tile 0
#pragma unroll
    for (int i = 0; i < 4; ++i) {
        cp16(smb + wdst[i], Wg + (size_t)wm[i] * KTOT + wq4[i]);
        cp16(smb + bdst[i], Bg + (size_t)bk[i] * C2 + bq4[i]);
    }
    CP_COMMIT();

    for (int kt = 0; kt < NT; ++kt) {
        int cur = kt & 1;
        if (kt + 1 < NT) {
            int nxt = (kt + 1) & 1;
            uint32_t woff = (uint32_t)(nxt * WS_BUF * 4);
            uint32_t boff = (uint32_t)(nxt * BS_BUF * 4);
            int kg = (kt + 1) * KT;
#pragma unroll
            for (int i = 0; i < 4; ++i) {
                cp16(smb + woff + wdst[i], Wg + (size_t)wm[i] * KTOT + kg + wq4[i]);
                cp16(smb + boff + bdst[i], Bg + (size_t)(kg + bk[i]) * C2 + bq4[i]);
            }
            CP_COMMIT();
            CP_WAIT(1);
        } else {
            CP_WAIT(0);
        }
        __syncthreads();

        const float* Ws = sm + cur * WS_BUF;
        const float* Bs = sm + 2 * WS_BUF + cur * BS_BUF;
#pragma unroll
        for (int ks = 0; ks < 4; ++ks) {
            int kb = ks * 8;
            uint32_t a[2][4], bb[8][2];
#pragma unroll
            for (int mt = 0; mt < 2; ++mt) {
                const float* ab = Ws + (warp_m + mt * 16 + g) * WS_STRIDE + kb + kq;
                a[mt][0] = __float_as_uint(ab[0]);
                a[mt][1] = __float_as_uint(ab[8 * WS_STRIDE]);
                a[mt][2] = __float_as_uint(ab[4]);
                a[mt][3] = __float_as_uint(ab[8 * WS_STRIDE + 4]);
            }
#pragma unroll
            for (int nt = 0; nt < 8; ++nt) {
                const float* bbp = Bs + (kb + kq) * BS_STRIDE + warp_n + nt * 8 + g;
                bb[nt][0] = __float_as_uint(bbp[0]);
                bb[nt][1] = __float_as_uint(bbp[4 * BS_STRIDE]);
            }
#pragma unroll
            for (int mt = 0; mt < 2; ++mt)
#pragma unroll
                for (int nt = 0; nt < 8; ++nt)
                    mma_tf32(acc[mt][nt], a[mt], bb[nt]);
        }
        __syncthreads();
    }

    // epilogue -> g_yp[s]
    float* out = g_yp[s] + ((size_t)b * OUTCH + o0) * C2 + c0;
#pragma unroll
    for (int mt = 0; mt < 2; ++mt) {
        int r0 = warp_m + mt * 16 + g;
#pragma unroll
        for (int nt = 0; nt < 8; ++nt) {
            int col = warp_n + nt * 8 + kq * 2;
            *(float2*)(out + (size_t)r0 * C2 + col)       = make_float2(acc[mt][nt][0], acc[mt][nt][1]);
            *(float2*)(out + (size_t)(r0 + 8) * C2 + col) = make_float2(acc[mt][nt][2], acc[mt][nt][3]);
        }
    }
}

// ---------------- kernel 4: reduce partials + bias + BN stats ----------------
__global__ void reduce_kernel(const float* __restrict__ b1) {
    int c = threadIdx.x;
    int row0 = blockIdx.x * 16;
    float s1 = 0.f, s2 = 0.f;
    for (int r = 0; r < 16; ++r) {
        int row = row0 + r;
        int o = row & (OUTCH - 1);
        size_t idx = (size_t)row * C2 + c;
        float v = b1[o];
#pragma unroll
        for (int s = 0; s < SPLITK; ++s) v += g_yp[s][idx];
        g_y[idx] = v;
        s1 += v;
        s2 = fmaf(v, v, s2);
    }
    atomicAdd(&g_sum[c], s1);
    atomicAdd(&g_sumsq[c], s2);
}

// ---------------- kernel 5: BN + ReLU ----------------
__global__ void bn_kernel(const float* __restrict__ gamma,
                          const float* __restrict__ beta,
                          float* __restrict__ out) {
    int c = threadIdx.x;
    int row = blockIdx.x;
    const float invN = 1.f / (BATCH * OUTCH);
    float mean = g_sum[c] * invN;
    float var  = fmaf(g_sumsq[c], invN, -mean * mean);
    float rstd = rsqrtf(var + BN_EPS);
    float v = g_y[(size_t)row * C2 + c];
    float r = fmaf(gamma[c] * rstd, v - mean, beta[c]);
    out[(size_t)row * C2 + c] = fmaxf(r, 0.f);
}

// ---------------- launcher ----------------
extern "C" void kernel_launch(void* const* d_in, const int* in_sizes, int n_in,
                              void* d_out, int out_size) {
    const float* x2    = (const float*)d_in[1];
    const float* xyz1  = (const float*)d_in[2];
    const float* xyz2  = (const float*)d_in[3];
    const float* W1    = (const float*)d_in[4];
    const float* b1    = (const float*)d_in[5];
    const float* gamma = (const float*)d_in[6];
    const float* beta  = (const float*)d_in[7];
    float* out = (float*)d_out;

    cudaFuncSetAttribute(gemm_mma_kernel,
                         cudaFuncAttributeMaxDynamicSharedMemorySize,
                         SMEM_FLOATS * 4);

    zero_stats_kernel<<<1, C2>>>();
    convW_kernel<<<(OUTCH * KTOT) / 1024, 256>>>(W1);
    topk_kernel<<<BATCH * 8, 256>>>(xyz1, xyz2);
    interp_kernel<<<(BATCH * N1) / 4, 256>>>(x2);
    gemm_mma_kernel<<<BATCH * 2 * 2 * SPLITK, 256, SMEM_FLOATS * 4>>>();
    reduce_kernel<<<(BATCH * OUTCH) / 16, C2>>>(b1);
    bn_kernel<<<BATCH * OUTCH, C2>>>(gamma, beta, out);
}

// round 6
// speedup vs baseline: 1.1922x; 1.1922x over previous
#include <cuda_runtime.h>
#include <cstdint>

// ---------------- problem constants ----------------
#define BATCH   16
#define N1      4096
#define N2      1024
#define C2      256
#define OUTCH   256
#define KTOT    4096
#define SPLITK  4
#define KPER    (KTOT/SPLITK)   // 1024
#define KT      32              // K tile
#define NT      (KPER/KT)       // 32 tiles
#define BN_EPS  1e-5f

// smem layout (floats): Ws[2][128*36], Bs[2][32*136]
// WS_STRIDE 36  -> A-frag LDS banks (4g+kq) mod 32 : conflict-free
// BS_STRIDE 136 -> B-frag LDS banks (8kq+g) mod 32 : conflict-free
#define WS_STRIDE 36
#define BS_STRIDE 136
#define WS_BUF    (128*WS_STRIDE)        // 4608 floats
#define BS_BUF    (32*BS_STRIDE)         // 4352 floats
#define SMEM_FLOATS (2*WS_BUF + 2*BS_BUF)  // 17920 floats = 71680 B

// ---------------- device scratch ----------------
__device__ int    g_idx[BATCH * N1 * 3];
__device__ float  g_w  [BATCH * N1 * 3];
__device__ float  g_Wtf[(size_t)OUTCH * KTOT];                 // 4 MB  tf32-rounded W
__device__ float  g_interp[(size_t)BATCH * N1 * C2];           // 67 MB tf32-rounded A[b][n][c]
__device__ float  g_yp[SPLITK][(size_t)BATCH * OUTCH * C2];    // 16 MB partials
__device__ float  g_y [(size_t)BATCH * OUTCH * C2];
__device__ float  g_sum[C2];
__device__ float  g_sumsq[C2];

// ---------------- helpers ----------------
__device__ __forceinline__ uint32_t smem_u32(const void* p) {
    uint32_t a;
    asm("{ .reg .u64 t; cvta.to.shared.u64 t, %1; cvt.u32.u64 %0, t; }" : "=r"(a) : "l"(p));
    return a;
}
__device__ __forceinline__ float tf32r(float x) {
    uint32_t u;
    asm("cvt.rna.tf32.f32 %0, %1;" : "=r"(u) : "f"(x));
    return __uint_as_float(u);
}
__device__ __forceinline__ void cp16(uint32_t dst, const void* src) {
    asm volatile("cp.async.cg.shared.global [%0], [%1], 16;" :: "r"(dst), "l"(src) : "memory");
}
#define CP_COMMIT()  asm volatile("cp.async.commit_group;" ::: "memory")
#define CP_WAIT(n)   asm volatile("cp.async.wait_group %0;" :: "n"(n) : "memory")

__device__ __forceinline__ void mma_tf32(float* d, const uint32_t* a, const uint32_t* b) {
    asm volatile(
        "mma.sync.aligned.m16n8k8.row.col.f32.tf32.tf32.f32 "
        "{%0,%1,%2,%3}, {%4,%5,%6,%7}, {%8,%9}, {%0,%1,%2,%3};"
        : "+f"(d[0]), "+f"(d[1]), "+f"(d[2]), "+f"(d[3])
        : "r"(a[0]), "r"(a[1]), "r"(a[2]), "r"(a[3]), "r"(b[0]), "r"(b[1]));
}

// ---------------- kernel 0: W -> tf32 copy + BN accumulator zeroing ----------------
__global__ void convW_kernel(const float* __restrict__ W1) {
    if (blockIdx.x == 0) {
        g_sum[threadIdx.x] = 0.f;
        g_sumsq[threadIdx.x] = 0.f;
    }
    int i = blockIdx.x * 256 + threadIdx.x;   // float4 index
    float4 v = ((const float4*)W1)[i];
    ((float4*)g_Wtf)[i] = make_float4(tf32r(v.x), tf32r(v.y), tf32r(v.z), tf32r(v.w));
}

// ---------------- kernel 1: 3-NN + weights (1 point / thread) ----------------
__global__ void topk_kernel(const float* __restrict__ xyz1,
                            const float* __restrict__ xyz2) {
    __shared__ float sx[N2], sy[N2], sz[N2];
    int b = blockIdx.x >> 4;
    int nchunk = blockIdx.x & 15;

    const float* p2 = xyz2 + (size_t)b * N2 * 3;
    for (int j = threadIdx.x; j < N2; j += 256) {
        sx[j] = p2[j * 3 + 0]; sy[j] = p2[j * 3 + 1]; sz[j] = p2[j * 3 + 2];
    }
    __syncthreads();

    int n = nchunk * 256 + threadIdx.x;
    const float* p1 = xyz1 + ((size_t)b * N1 + n) * 3;
    float px = p1[0], py = p1[1], pz = p1[2];

    float d0 = 3.4e38f, d1 = 3.4e38f, d2 = 3.4e38f;
    int   i0 = 0, i1 = 0, i2 = 0;
#pragma unroll 4
    for (int j = 0; j < N2; ++j) {
        float dx = px - sx[j], dy = py - sy[j], dz = pz - sz[j];
        float d = fmaf(dx, dx, fmaf(dy, dy, dz * dz));
        if (d < d2) {
            if (d < d1) {
                d2 = d1; i2 = i1;
                if (d < d0) { d1 = d0; i1 = i0; d0 = d; i0 = j; }
                else        { d1 = d;  i1 = j; }
            } else { d2 = d; i2 = j; }
        }
    }
    float r0 = 1.f / (d0 + 1e-8f), r1 = 1.f / (d1 + 1e-8f), r2 = 1.f / (d2 + 1e-8f);
    float inv = 1.f / (r0 + r1 + r2);
    size_t base = ((size_t)b * N1 + n) * 3;
    g_idx[base + 0] = i0; g_idx[base + 1] = i1; g_idx[base + 2] = i2;
    g_w  [base + 0] = r0 * inv; g_w[base + 1] = r1 * inv; g_w[base + 2] = r2 * inv;
}

// ---------------- kernel 2: interpolation (tf32-rounded) -> A[b][n][c] ----------------
__global__ void interp_kernel(const float* __restrict__ x2) {
    int pt   = blockIdx.x * 4 + (threadIdx.x >> 6);
    int lane = threadIdx.x & 63;
    int b = pt >> 12;

    size_t base = (size_t)pt * 3;
    int i0 = g_idx[base + 0], i1 = g_idx[base + 1], i2 = g_idx[base + 2];
    float w0 = g_w[base + 0], w1 = g_w[base + 1], w2 = g_w[base + 2];

    const float* xb = x2 + (size_t)b * N2 * C2;
    int c = lane * 4;
    float4 v0 = *(const float4*)(xb + (size_t)i0 * C2 + c);
    float4 v1 = *(const float4*)(xb + (size_t)i1 * C2 + c);
    float4 v2 = *(const float4*)(xb + (size_t)i2 * C2 + c);

    float4 r;
    r.x = tf32r(fmaf(w0, v0.x, fmaf(w1, v1.x, w2 * v2.x)));
    r.y = tf32r(fmaf(w0, v0.y, fmaf(w1, v1.y, w2 * v2.y)));
    r.z = tf32r(fmaf(w0, v0.z, fmaf(w1, v1.z, w2 * v2.z)));
    r.w = tf32r(fmaf(w0, v0.w, fmaf(w1, v1.w, w2 * v2.w)));
    *(float4*)(g_interp + (size_t)pt * C2 + c) = r;
}

// ---------------- kernel 3: tf32 mma.sync GEMM ----------------
// grid = b(16) x Mtile(2) x Ntile(2) x splitK(4) = 256 CTAs, 256 threads
__global__ __launch_bounds__(256, 2)
void gemm_mma_kernel() {
    extern __shared__ float sm[];
    const uint32_t smb = smem_u32(sm);

    int bid = blockIdx.x;
    int s   = bid & 3;
    int mtb = (bid >> 2) & 1;
    int ntb = (bid >> 3) & 1;
    int b   = bid >> 4;
    int o0 = mtb * 128, c0 = ntb * 128, k0 = s * KPER;

    int t = threadIdx.x;
    int w = t >> 5, lane = t & 31;
    int g = lane >> 2, kq = lane & 3;
    int warp_m = (w & 3) * 32;
    int warp_n = (w >> 2) * 64;

    const float* Wg = g_Wtf + (size_t)o0 * KTOT + k0;
    const float* Bg = g_interp + ((size_t)b * N1 + k0) * C2 + c0;

    // per-thread load slots (4 x float4 each for W and B)
    int wm[4], wq4[4], bk[4], bq4[4];
    uint32_t wdst[4], bdst[4];
#pragma unroll
    for (int i = 0; i < 4; ++i) {
        int li = i * 256 + t;
        wm[i]  = li >> 3;        wq4[i] = (li & 7) * 4;
        bk[i]  = li >> 5;        bq4[i] = (li & 31) * 4;
        wdst[i] = (uint32_t)((wm[i] * WS_STRIDE + wq4[i]) * 4);
        bdst[i] = (uint32_t)((2 * WS_BUF + bk[i] * BS_STRIDE + bq4[i]) * 4);
    }

    float acc[2][8][4];
#pragma unroll
    for (int mt = 0; mt < 2; ++mt)
#pragma unroll
        for (int nt = 0; nt < 8; ++nt)
#pragma unroll
            for (int r = 0; r < 4; ++r) acc[mt][nt][r] = 0.f;

    // issue tile 0
#pragma unroll
    for (int i = 0; i < 4; ++i) {
        cp16(smb + wdst[i], Wg + (size_t)wm[i] * KTOT + wq4[i]);
        cp16(smb + bdst[i], Bg + (size_t)bk[i] * C2 + bq4[i]);
    }
    CP_COMMIT();

    for (int kt = 0; kt < NT; ++kt) {
        int cur = kt & 1;
        if (kt + 1 < NT) {
            int nxt = (kt + 1) & 1;
            uint32_t woff = (uint32_t)(nxt * WS_BUF * 4);
            uint32_t boff = (uint32_t)(nxt * BS_BUF * 4);
            int kg = (kt + 1) * KT;
#pragma unroll
            for (int i = 0; i < 4; ++i) {
                cp16(smb + woff + wdst[i], Wg + (size_t)wm[i] * KTOT + kg + wq4[i]);
                cp16(smb + boff + bdst[i], Bg + (size_t)(kg + bk[i]) * C2 + bq4[i]);
            }
            CP_COMMIT();
            CP_WAIT(1);
        } else {
            CP_WAIT(0);
        }
        __syncthreads();

        const float* Ws = sm + cur * WS_BUF;
        const float* Bs = sm + 2 * WS_BUF + cur * BS_BUF;
#pragma unroll
        for (int ks = 0; ks < 4; ++ks) {
            int kb = ks * 8;
            uint32_t a[2][4], bb[8][2];
#pragma unroll
            for (int mt = 0; mt < 2; ++mt) {
                const float* ab = Ws + (warp_m + mt * 16 + g) * WS_STRIDE + kb + kq;
                a[mt][0] = __float_as_uint(ab[0]);
                a[mt][1] = __float_as_uint(ab[8 * WS_STRIDE]);
                a[mt][2] = __float_as_uint(ab[4]);
                a[mt][3] = __float_as_uint(ab[8 * WS_STRIDE + 4]);
            }
#pragma unroll
            for (int nt = 0; nt < 8; ++nt) {
                const float* bbp = Bs + (kb + kq) * BS_STRIDE + warp_n + nt * 8 + g;
                bb[nt][0] = __float_as_uint(bbp[0]);
                bb[nt][1] = __float_as_uint(bbp[4 * BS_STRIDE]);
            }
#pragma unroll
            for (int mt = 0; mt < 2; ++mt)
#pragma unroll
                for (int nt = 0; nt < 8; ++nt)
                    mma_tf32(acc[mt][nt], a[mt], bb[nt]);
        }
        __syncthreads();
    }

    // epilogue -> g_yp[s]
    float* out = g_yp[s] + ((size_t)b * OUTCH + o0) * C2 + c0;
#pragma unroll
    for (int mt = 0; mt < 2; ++mt) {
        int r0 = warp_m + mt * 16 + g;
#pragma unroll
        for (int nt = 0; nt < 8; ++nt) {
            int col = warp_n + nt * 8 + kq * 2;
            *(float2*)(out + (size_t)r0 * C2 + col)       = make_float2(acc[mt][nt][0], acc[mt][nt][1]);
            *(float2*)(out + (size_t)(r0 + 8) * C2 + col) = make_float2(acc[mt][nt][2], acc[mt][nt][3]);
        }
    }
}

// ---------------- kernel 4: reduce partials + bias + BN stats ----------------
__global__ void reduce_kernel(const float* __restrict__ b1) {
    int c = threadIdx.x;
    int row0 = blockIdx.x * 16;
    float s1 = 0.f, s2 = 0.f;
    for (int r = 0; r < 16; ++r) {
        int row = row0 + r;
        int o = row & (OUTCH - 1);
        size_t idx = (size_t)row * C2 + c;
        float v = b1[o];
#pragma unroll
        for (int s = 0; s < SPLITK; ++s) v += g_yp[s][idx];
        g_y[idx] = v;
        s1 += v;
        s2 = fmaf(v, v, s2);
    }
    atomicAdd(&g_sum[c], s1);
    atomicAdd(&g_sumsq[c], s2);
}

// ---------------- kernel 5: BN + ReLU ----------------
__global__ void bn_kernel(const float* __restrict__ gamma,
                          const float* __restrict__ beta,
                          float* __restrict__ out) {
    int c = threadIdx.x;
    int row = blockIdx.x;
    const float invN = 1.f / (BATCH * OUTCH);
    float mean = g_sum[c] * invN;
    float var  = fmaf(g_sumsq[c], invN, -mean * mean);
    float rstd = rsqrtf(var + BN_EPS);
    float v = g_y[(size_t)row * C2 + c];
    float r = fmaf(gamma[c] * rstd, v - mean, beta[c]);
    out[(size_t)row * C2 + c] = fmaxf(r, 0.f);
}

// ---------------- launcher ----------------
extern "C" void kernel_launch(void* const* d_in, const int* in_sizes, int n_in,
                              void* d_out, int out_size) {
    const float* x2    = (const float*)d_in[1];
    const float* xyz1  = (const float*)d_in[2];
    const float* xyz2  = (const float*)d_in[3];
    const float* W1    = (const float*)d_in[4];
    const float* b1    = (const float*)d_in[5];
    const float* gamma = (const float*)d_in[6];
    const float* beta  = (const float*)d_in[7];
    float* out = (float*)d_out;

    cudaFuncSetAttribute(gemm_mma_kernel,
                         cudaFuncAttributeMaxDynamicSharedMemorySize,
                         SMEM_FLOATS * 4);

    convW_kernel<<<(OUTCH * KTOT) / 1024, 256>>>(W1);
    topk_kernel<<<BATCH * 16, 256>>>(xyz1, xyz2);
    interp_kernel<<<(BATCH * N1) / 4, 256>>>(x2);
    gemm_mma_kernel<<<BATCH * 2 * 2 * SPLITK, 256, SMEM_FLOATS * 4>>>();
    reduce_kernel<<<(BATCH * OUTCH) / 16, C2>>>(b1);
    bn_kernel<<<BATCH * OUTCH, C2>>>(gamma, beta, out);
}

// round 7
// speedup vs baseline: 1.2644x; 1.0605x over previous
#include <cuda_runtime.h>
#include <cstdint>

// ---------------- problem constants ----------------
#define BATCH   16
#define N1      4096
#define N2      1024
#define C2      256
#define OUTCH   256
#define KTOT    4096
#define SPLITK  4
#define KPER    (KTOT/SPLITK)   // 1024
#define KT      32              // K tile
#define NT      (KPER/KT)       // 32 tiles
#define BN_EPS  1e-5f

// smem: 3 stages of (Ws[128*36] + Bs[32*136])
#define WS_STRIDE 36
#define BS_STRIDE 136
#define WS_BUF    (128*WS_STRIDE)        // 4608 floats
#define BS_BUF    (32*BS_STRIDE)         // 4352 floats
#define STG_FLOATS (WS_BUF + BS_BUF)     // 8960 floats = 35840 B
#define SMEM_FLOATS (3*STG_FLOATS)       // 26880 floats = 107520 B

// ---------------- device scratch ----------------
__device__ int    g_idx[BATCH * N1 * 3];
__device__ float  g_w  [BATCH * N1 * 3];
__device__ float  g_Wtf[(size_t)OUTCH * KTOT];                 // 4 MB  tf32-rounded W
__device__ float  g_interp[(size_t)BATCH * N1 * C2];           // 67 MB tf32-rounded A[b][n][c]
__device__ float  g_yp[SPLITK][(size_t)BATCH * OUTCH * C2];    // 16 MB partials
__device__ float  g_y [(size_t)BATCH * OUTCH * C2];
__device__ float  g_sum[C2];
__device__ float  g_sumsq[C2];

// ---------------- helpers ----------------
__device__ __forceinline__ uint32_t smem_u32(const void* p) {
    uint32_t a;
    asm("{ .reg .u64 t; cvta.to.shared.u64 t, %1; cvt.u32.u64 %0, t; }" : "=r"(a) : "l"(p));
    return a;
}
__device__ __forceinline__ float tf32r(float x) {
    uint32_t u;
    asm("cvt.rna.tf32.f32 %0, %1;" : "=r"(u) : "f"(x));
    return __uint_as_float(u);
}
__device__ __forceinline__ void cp16(uint32_t dst, const void* src) {
    asm volatile("cp.async.cg.shared.global [%0], [%1], 16;" :: "r"(dst), "l"(src) : "memory");
}
#define CP_COMMIT()  asm volatile("cp.async.commit_group;" ::: "memory")
#define CP_WAIT(n)   asm volatile("cp.async.wait_group %0;" :: "n"(n) : "memory")

__device__ __forceinline__ void mma_tf32(float* d, const uint32_t* a, const uint32_t* b) {
    asm volatile(
        "mma.sync.aligned.m16n8k8.row.col.f32.tf32.tf32.f32 "
        "{%0,%1,%2,%3}, {%4,%5,%6,%7}, {%8,%9}, {%0,%1,%2,%3};"
        : "+f"(d[0]), "+f"(d[1]), "+f"(d[2]), "+f"(d[3])
        : "r"(a[0]), "r"(a[1]), "r"(a[2]), "r"(a[3]), "r"(b[0]), "r"(b[1]));
}

// ---------------- kernel 0: W -> tf32 copy + BN accumulator zeroing ----------------
__global__ void convW_kernel(const float* __restrict__ W1) {
    if (blockIdx.x == 0) {
        g_sum[threadIdx.x] = 0.f;
        g_sumsq[threadIdx.x] = 0.f;
    }
    int i = blockIdx.x * 256 + threadIdx.x;   // float4 index
    float4 v = ((const float4*)W1)[i];
    ((float4*)g_Wtf)[i] = make_float4(tf32r(v.x), tf32r(v.y), tf32r(v.z), tf32r(v.w));
}

// ---------------- kernel 1: 3-NN + weights (dot-product form, packed smem) ----------------
__global__ void topk_kernel(const float* __restrict__ xyz1,
                            const float* __restrict__ xyz2) {
    __shared__ float4 sq[N2];   // (qx, qy, qz, |q|^2)
    int b = blockIdx.x >> 4;
    int nchunk = blockIdx.x & 15;

    const float* p2 = xyz2 + (size_t)b * N2 * 3;
    for (int j = threadIdx.x; j < N2; j += 256) {
        float qx = p2[j * 3 + 0], qy = p2[j * 3 + 1], qz = p2[j * 3 + 2];
        sq[j] = make_float4(qx, qy, qz, fmaf(qx, qx, fmaf(qy, qy, qz * qz)));
    }
    __syncthreads();

    int n = nchunk * 256 + threadIdx.x;
    const float* p1 = xyz1 + ((size_t)b * N1 + n) * 3;
    float px = p1[0], py = p1[1], pz = p1[2];
    float px2 = -2.f * px, py2 = -2.f * py, pz2 = -2.f * pz;
    float pp = fmaf(px, px, fmaf(py, py, pz * pz));

    // min-3 on d' = |q|^2 - 2 p.q  (shift by |p|^2 preserves ordering)
    float d0 = 3.4e38f, d1 = 3.4e38f, d2 = 3.4e38f;
    int   i0 = 0, i1 = 0, i2 = 0;
#pragma unroll 8
    for (int j = 0; j < N2; ++j) {
        float4 q = sq[j];
        float d = fmaf(px2, q.x, fmaf(py2, q.y, fmaf(pz2, q.z, q.w)));
        if (d < d2) {
            if (d < d1) {
                d2 = d1; i2 = i1;
                if (d < d0) { d1 = d0; i1 = i0; d0 = d; i0 = j; }
                else        { d1 = d;  i1 = j; }
            } else { d2 = d; i2 = j; }
        }
    }
    float r0 = 1.f / (d0 + pp + 1e-8f);
    float r1 = 1.f / (d1 + pp + 1e-8f);
    float r2 = 1.f / (d2 + pp + 1e-8f);
    float inv = 1.f / (r0 + r1 + r2);
    size_t base = ((size_t)b * N1 + n) * 3;
    g_idx[base + 0] = i0; g_idx[base + 1] = i1; g_idx[base + 2] = i2;
    g_w  [base + 0] = r0 * inv; g_w[base + 1] = r1 * inv; g_w[base + 2] = r2 * inv;
}

// ---------------- kernel 2: interpolation (2 points / thread, tf32-rounded) ----------------
__global__ void interp_kernel(const float* __restrict__ x2) {
    int pair = threadIdx.x >> 6;            // 0..3
    int lane = threadIdx.x & 63;
    int ptA  = blockIdx.x * 8 + pair * 2;   // global (b*N1+n)
    int ptB  = ptA + 1;
    int b = ptA >> 12;
    int c = lane * 4;

    size_t baseA = (size_t)ptA * 3, baseB = (size_t)ptB * 3;
    int ai0 = g_idx[baseA + 0], ai1 = g_idx[baseA + 1], ai2 = g_idx[baseA + 2];
    int bi0 = g_idx[baseB + 0], bi1 = g_idx[baseB + 1], bi2 = g_idx[baseB + 2];
    float aw0 = g_w[baseA + 0], aw1 = g_w[baseA + 1], aw2 = g_w[baseA + 2];
    float bw0 = g_w[baseB + 0], bw1 = g_w[baseB + 1], bw2 = g_w[baseB + 2];

    const float* xb = x2 + (size_t)b * N2 * C2 + c;
    float4 a0 = *(const float4*)(xb + (size_t)ai0 * C2);
    float4 a1 = *(const float4*)(xb + (size_t)ai1 * C2);
    float4 a2 = *(const float4*)(xb + (size_t)ai2 * C2);
    float4 b0 = *(const float4*)(xb + (size_t)bi0 * C2);
    float4 b1 = *(const float4*)(xb + (size_t)bi1 * C2);
    float4 b2 = *(const float4*)(xb + (size_t)bi2 * C2);

    float4 ra, rb;
    ra.x = tf32r(fmaf(aw0, a0.x, fmaf(aw1, a1.x, aw2 * a2.x)));
    ra.y = tf32r(fmaf(aw0, a0.y, fmaf(aw1, a1.y, aw2 * a2.y)));
    ra.z = tf32r(fmaf(aw0, a0.z, fmaf(aw1, a1.z, aw2 * a2.z)));
    ra.w = tf32r(fmaf(aw0, a0.w, fmaf(aw1, a1.w, aw2 * a2.w)));
    rb.x = tf32r(fmaf(bw0, b0.x, fmaf(bw1, b1.x, bw2 * b2.x)));
    rb.y = tf32r(fmaf(bw0, b0.y, fmaf(bw1, b1.y, bw2 * b2.y)));
    rb.z = tf32r(fmaf(bw0, b0.z, fmaf(bw1, b1.z, bw2 * b2.z)));
    rb.w = tf32r(fmaf(bw0, b0.w, fmaf(bw1, b1.w, bw2 * b2.w)));
    *(float4*)(g_interp + (size_t)ptA * C2 + c) = ra;
    *(float4*)(g_interp + (size_t)ptB * C2 + c) = rb;
}

// ---------------- kernel 3: tf32 mma.sync GEMM, 3-stage cp.async pipeline ----------------
// grid = b(16) x Mtile(2) x Ntile(2) x splitK(4) = 256 CTAs, 256 threads
__global__ __launch_bounds__(256, 2)
void gemm_mma_kernel() {
    extern __shared__ float sm[];
    const uint32_t smb = smem_u32(sm);

    int bid = blockIdx.x;
    int s   = bid & 3;
    int mtb = (bid >> 2) & 1;
    int ntb = (bid >> 3) & 1;
    int b   = bid >> 4;
    int o0 = mtb * 128, c0 = ntb * 128, k0 = s * KPER;

    int t = threadIdx.x;
    int w = t >> 5, lane = t & 31;
    int g = lane >> 2, kq = lane & 3;
    int warp_m = (w & 3) * 32;
    int warp_n = (w >> 2) * 64;

    const float* Wg = g_Wtf + (size_t)o0 * KTOT + k0;
    const float* Bg = g_interp + ((size_t)b * N1 + k0) * C2 + c0;

    // per-thread load slots (4 x float4 each for W and B), offsets within a stage
    int wm[4], wq4[4], bk[4], bq4[4];
    uint32_t wdst[4], bdst[4];
#pragma unroll
    for (int i = 0; i < 4; ++i) {
        int li = i * 256 + t;
        wm[i]  = li >> 3;        wq4[i] = (li & 7) * 4;
        bk[i]  = li >> 5;        bq4[i] = (li & 31) * 4;
        wdst[i] = (uint32_t)((wm[i] * WS_STRIDE + wq4[i]) * 4);
        bdst[i] = (uint32_t)((WS_BUF + bk[i] * BS_STRIDE + bq4[i]) * 4);
    }

    float acc[2][8][4];
#pragma unroll
    for (int mt = 0; mt < 2; ++mt)
#pragma unroll
        for (int nt = 0; nt < 8; ++nt)
#pragma unroll
            for (int r = 0; r < 4; ++r) acc[mt][nt][r] = 0.f;

    // prologue: issue stages for tiles 0 and 1
#pragma unroll
    for (int pre = 0; pre < 2; ++pre) {
        uint32_t sb = smb + (uint32_t)(pre * STG_FLOATS * 4);
        int kg = pre * KT;
#pragma unroll
        for (int i = 0; i < 4; ++i) {
            cp16(sb + wdst[i], Wg + (size_t)wm[i] * KTOT + kg + wq4[i]);
            cp16(sb + bdst[i], Bg + (size_t)(kg + bk[i]) * C2 + bq4[i]);
        }
        CP_COMMIT();
    }

    int cur = 0;                 // stage of tile t
    int nxt2 = 2 * STG_FLOATS;   // stage (floats offset) of tile t+2
    for (int kt = 0; kt < NT; ++kt) {
        if (kt == NT - 1) { CP_WAIT(0); } else { CP_WAIT(1); }
        __syncthreads();

        if (kt + 2 < NT) {
            uint32_t sb = smb + (uint32_t)(nxt2 * 4);
            int kg = (kt + 2) * KT;
#pragma unroll
            for (int i = 0; i < 4; ++i) {
                cp16(sb + wdst[i], Wg + (size_t)wm[i] * KTOT + kg + wq4[i]);
                cp16(sb + bdst[i], Bg + (size_t)(kg + bk[i]) * C2 + bq4[i]);
            }
            CP_COMMIT();
        }

        const float* Ws = sm + cur;
        const float* Bs = sm + cur + WS_BUF;
#pragma unroll
        for (int ks = 0; ks < 4; ++ks) {
            int kb = ks * 8;
            uint32_t a[2][4], bb[8][2];
#pragma unroll
            for (int mt = 0; mt < 2; ++mt) {
                const float* ab = Ws + (warp_m + mt * 16 + g) * WS_STRIDE + kb + kq;
                a[mt][0] = __float_as_uint(ab[0]);
                a[mt][1] = __float_as_uint(ab[8 * WS_STRIDE]);
                a[mt][2] = __float_as_uint(ab[4]);
                a[mt][3] = __float_as_uint(ab[8 * WS_STRIDE + 4]);
            }
#pragma unroll
            for (int nt = 0; nt < 8; ++nt) {
                const float* bbp = Bs + (kb + kq) * BS_STRIDE + warp_n + nt * 8 + g;
                bb[nt][0] = __float_as_uint(bbp[0]);
                bb[nt][1] = __float_as_uint(bbp[4 * BS_STRIDE]);
            }
#pragma unroll
            for (int mt = 0; mt < 2; ++mt)
#pragma unroll
                for (int nt = 0; nt < 8; ++nt)
                    mma_tf32(acc[mt][nt], a[mt], bb[nt]);
        }

        cur  += STG_FLOATS; if (cur  == 3 * STG_FLOATS) cur  = 0;
        nxt2 += STG_FLOATS; if (nxt2 == 3 * STG_FLOATS) nxt2 = 0;
    }

    // epilogue -> g_yp[s]
    float* out = g_yp[s] + ((size_t)b * OUTCH + o0) * C2 + c0;
#pragma unroll
    for (int mt = 0; mt < 2; ++mt) {
        int r0 = warp_m + mt * 16 + g;
#pragma unroll
        for (int nt = 0; nt < 8; ++nt) {
            int col = warp_n + nt * 8 + kq * 2;
            *(float2*)(out + (size_t)r0 * C2 + col)       = make_float2(acc[mt][nt][0], acc[mt][nt][1]);
            *(float2*)(out + (size_t)(r0 + 8) * C2 + col) = make_float2(acc[mt][nt][2], acc[mt][nt][3]);
        }
    }
}

// ---------------- kernel 4: reduce partials + bias + BN stats ----------------
__global__ void reduce_kernel(const float* __restrict__ b1) {
    int c = threadIdx.x;
    int row0 = blockIdx.x * 16;
    float s1 = 0.f, s2 = 0.f;
    for (int r = 0; r < 16; ++r) {
        int row = row0 + r;
        int o = row & (OUTCH - 1);
        size_t idx = (size_t)row * C2 + c;
        float v = b1[o];
#pragma unroll
        for (int s = 0; s < SPLITK; ++s) v += g_yp[s][idx];
        g_y[idx] = v;
        s1 += v;
        s2 = fmaf(v, v, s2);
    }
    atomicAdd(&g_sum[c], s1);
    atomicAdd(&g_sumsq[c], s2);
}

// ---------------- kernel 5: BN + ReLU ----------------
__global__ void bn_kernel(const float* __restrict__ gamma,
                          const float* __restrict__ beta,
                          float* __restrict__ out) {
    int c = threadIdx.x;
    int row = blockIdx.x;
    const float invN = 1.f / (BATCH * OUTCH);
    float mean = g_sum[c] * invN;
    float var  = fmaf(g_sumsq[c], invN, -mean * mean);
    float rstd = rsqrtf(var + BN_EPS);
    float v = g_y[(size_t)row * C2 + c];
    float r = fmaf(gamma[c] * rstd, v - mean, beta[c]);
    out[(size_t)row * C2 + c] = fmaxf(r, 0.f);
}

// ---------------- launcher ----------------
extern "C" void kernel_launch(void* const* d_in, const int* in_sizes, int n_in,
                              void* d_out, int out_size) {
    const float* x2    = (const float*)d_in[1];
    const float* xyz1  = (const float*)d_in[2];
    const float* xyz2  = (const float*)d_in[3];
    const float* W1    = (const float*)d_in[4];
    const float* b1    = (const float*)d_in[5];
    const float* gamma = (const float*)d_in[6];
    const float* beta  = (const float*)d_in[7];
    float* out = (float*)d_out;

    cudaFuncSetAttribute(gemm_mma_kernel,
                         cudaFuncAttributeMaxDynamicSharedMemorySize,
                         SMEM_FLOATS * 4);

    convW_kernel<<<(OUTCH * KTOT) / 1024, 256>>>(W1);
    topk_kernel<<<BATCH * 16, 256>>>(xyz1, xyz2);
    interp_kernel<<<(BATCH * N1) / 8, 256>>>(x2);
    gemm_mma_kernel<<<BATCH * 2 * 2 * SPLITK, 256, SMEM_FLOATS * 4>>>();
    reduce_kernel<<<(BATCH * OUTCH) / 16, C2>>>(b1);
    bn_kernel<<<BATCH * OUTCH, C2>>>(gamma, beta, out);
}